// round 16
// baseline (speedup 1.0000x reference)
#include <cuda_runtime.h>
#include <cuda_fp16.h>
#include <mma.h>
using namespace nvcuda;

#define NN 50000
#define EE 800000
#define EP (EE + NN)
#define HH 4
#define CC 32
#define HC 128
#define EDIM 8
#define NRELS 16
#define NLAYERS 3
#define HID 100

typedef unsigned long long ull;

static_assert(NN % 8 == 0, "agg blocks must be full");

// ---------- scratch (device globals; g_counts/g_hist zeroed steady-state) ----------
__device__ __half g_hh[NN * HC];
__device__ float g_xA[NN * HC];
__device__ float g_xB[NN * HC];
__device__ float g_ssrc[NN * HH];
__device__ float g_sdst[NN * HH];
__device__ int   g_rowstart[NN + 1];
__device__ int   g_counts[NN];
__device__ int   g_cursor[NN];
__device__ unsigned g_edgep[EP];        // src | (type<<16), sorted by dst
__device__ float g_serel[NLAYERS * (NRELS + 1) * HH];
__device__ float g_w0sum[HC];
__device__ float g_k0[8];
__device__ int   g_hist[NRELS];

// ---------- build: counts + type histogram (counts arrive zeroed) ----------
__global__ void k_histcount(const int* __restrict__ ei, const int* __restrict__ et) {
    __shared__ int sh[NRELS];
    if (threadIdx.x < NRELS) sh[threadIdx.x] = 0;
    __syncthreads();
    int i = blockIdx.x * blockDim.x + threadIdx.x;
    if (i < EE) {
        atomicAdd(&g_counts[ei[EE + i]], 1);
        atomicAdd(&sh[et[i]], 1);
    }
    __syncthreads();
    if (threadIdx.x < NRELS) atomicAdd(&g_hist[threadIdx.x], sh[threadIdx.x]);
}

// ---------- fused: exclusive scan (+1 self-loop) THEN tiny precompute ----------
__global__ void k_scanpre(const float* __restrict__ W0, const float* __restrict__ Wedge,
                          const float* __restrict__ attE, const float* __restrict__ eemb,
                          const float* __restrict__ attS, const float* __restrict__ attD) {
    __shared__ int ss[1024];
    __shared__ float su[NLAYERS * HH * EDIM];
    __shared__ float sea[EDIM];
    __shared__ float sw0[HC];
    const int CH = (NN + 1023) / 1024;
    int t = threadIdx.x;
    int w = t >> 5, lane = t & 31;

    // ---- scan phase ----
    int beg = t * CH;
    int end = min(beg + CH, NN);
    int s = 0;
    for (int i = beg; i < end; i++) s += g_counts[i] + 1;
    ss[t] = s;
    __syncthreads();
    for (int off = 1; off < 1024; off <<= 1) {
        int v = 0;
        if (t >= off) v = ss[t - off];
        __syncthreads();
        ss[t] += v;
        __syncthreads();
    }
    int run = (t == 0) ? 0 : ss[t - 1];
    for (int i = beg; i < end; i++) {
        g_rowstart[i] = run;
        g_cursor[i]   = run;
        run += g_counts[i] + 1;
    }
    if (t == 0) g_rowstart[NN] = EP;

    // ---- pre phase ----
    if (t < HC) {
        float v = 0.f;
        for (int c = 0; c < CC; c++) v += W0[c * HC + t];
        g_w0sum[t] = v;
        sw0[t] = v;
    }
    for (int e = w; e < NLAYERS * HH * EDIM; e += 32) {
        int l = e >> 5;
        int rem = e & 31;
        int h = rem >> 3;
        int d = rem & 7;
        float v = Wedge[(l * EDIM + d) * HC + h * CC + lane] * attE[l * HC + h * CC + lane];
#pragma unroll
        for (int off = 16; off; off >>= 1) v += __shfl_xor_sync(0xffffffffu, v, off);
        if (lane == 0) su[e] = v;
    }
    if (t < EDIM) {
        float f = 0.f;
        for (int rr = 0; rr < NRELS; rr++)
            f += (float)g_hist[rr] * eemb[rr * EDIM + t];
        sea[t] = f / (float)EE;
    }
    __syncthreads();
    if (t < NLAYERS * (NRELS + 1) * HH) {
        int l = t / ((NRELS + 1) * HH);
        int rem = t % ((NRELS + 1) * HH);
        int r = rem / HH;
        int h = rem % HH;
        float v = 0.f;
#pragma unroll
        for (int d = 0; d < EDIM; d++) {
            float ea = (r < NRELS) ? eemb[r * EDIM + d] : sea[d];
            v += ea * su[l * 32 + h * EDIM + d];
        }
        g_serel[t] = v;
    }
    if (t < 8) {
        int h = t & 3;
        const float* av = (t < 4) ? attS : attD;
        float v = 0.f;
        for (int c = 0; c < CC; c++) v += sw0[h * CC + c] * av[h * CC + c];
        g_k0[t] = v;
    }
}

// ---------- scatter edges into dst-CSR (single scattered store) ----------
__global__ void k_scatter(const int* __restrict__ ei, const int* __restrict__ et) {
    int i = blockIdx.x * blockDim.x + threadIdx.x;
    if (i < EE) {
        int d = ei[EE + i];
        int p = atomicAdd(&g_cursor[d], 1);
        g_edgep[p] = (unsigned)ei[i] | ((unsigned)et[i] << 16);
    } else if (i < EP) {
        int n = i - EE;
        int p = atomicAdd(&g_cursor[n], 1);
        g_edgep[p] = (unsigned)n | ((unsigned)NRELS << 16);
    }
}

// ---------- layer-0 aggregation: rank-1; edges split across the 8 lanes of
// each head group, butterfly merge. Re-zeroes g_counts / g_hist. ----------
__global__ void __launch_bounds__(256) k_agg0(const float* __restrict__ x,
                                              const float* __restrict__ bias,
                                              float* __restrict__ xout) {
    __shared__ float sser[(NRELS + 1) * HH];
    int t = threadIdx.x;
    if (t < (NRELS + 1) * HH) sser[t] = g_serel[t];
    if (blockIdx.x == 0 && t < NRELS) g_hist[t] = 0;
    __syncthreads();
    int warp = t >> 5, lane = t & 31;
    int n = blockIdx.x * 8 + warp;
    if (n >= NN) return;
    if (lane == 0) g_counts[n] = 0;
    int hd = lane >> 3;
    int sub = lane & 7;
    float4 w4 = ((const float4*)g_w0sum)[lane];
    float k0s = g_k0[hd];
    int beg = g_rowstart[n], end = g_rowstart[n + 1];
    float sdv = x[n] * g_k0[4 + hd];
    float ds = 0.f, sx = 0.f;

    for (int e = beg + sub; e < end; e += 8) {
        unsigned p = g_edgep[e];
        float xs = x[p & 0xFFFFu];
        float a = xs * k0s + sdv + sser[(p >> 16) * HH + hd];
        a = (a > 0.f) ? a : 0.2f * a;
        float w = __expf(a);
        ds += w;
        sx += w * xs;
    }
#pragma unroll
    for (int off = 1; off < 8; off <<= 1) {
        ds += __shfl_xor_sync(0xffffffffu, ds, off);
        sx += __shfl_xor_sync(0xffffffffu, sx, off);
    }
    float s = sx / (ds + 1e-16f);
    float4 b4 = ((const float4*)bias)[lane];
    float4 o = make_float4(fmaxf(s * w4.x + b4.x, 0.f), fmaxf(s * w4.y + b4.y, 0.f),
                           fmaxf(s * w4.z + b4.z, 0.f), fmaxf(s * w4.w + b4.w, 0.f));
    ((float4*)xout)[n * 32 + lane] = o;
}

// ---------- layers 1,2 aggregation: in-block scoring (dst derived from CSR
// position, sdst staged in smem) + gather ----------
#define ACHUNK 512
__global__ void __launch_bounds__(256) k_agg(const float* __restrict__ bias,
                                             const float* __restrict__ xprev,
                                             float* __restrict__ xout, int layer) {
    __shared__ unsigned sp[ACHUNK];
    __shared__ float4 sw4[ACHUNK];
    __shared__ float4 sser[NRELS + 1];
    __shared__ float4 ssd[8];
    int t = threadIdx.x;
    if (t < NRELS + 1)
        sser[t] = *(const float4*)&g_serel[layer * (NRELS + 1) * HH + t * HH];
    int warp = t >> 5, lane = t & 31;
    int b0 = blockIdx.x * 8;
    int n = b0 + warp;
    int hd = lane >> 3;
    int beg = g_rowstart[n], end = g_rowstart[n + 1];
    int bbeg = g_rowstart[b0];
    int bend = g_rowstart[b0 + 8];
    if (t < 8) ssd[t] = *(const float4*)(g_sdst + (b0 + t) * HH);
    // per-thread copy of row boundaries for branchless dst derivation
    int r1 = g_rowstart[b0 + 1], r2 = g_rowstart[b0 + 2], r3 = g_rowstart[b0 + 3];
    int r4 = g_rowstart[b0 + 4], r5 = g_rowstart[b0 + 5], r6 = g_rowstart[b0 + 6];
    int r7 = g_rowstart[b0 + 7];
    const float* swf = (const float*)sw4;
    float ds0 = 0.f, ds1 = 0.f;
    float4 ac0 = make_float4(0.f, 0.f, 0.f, 0.f);
    float4 ac1 = make_float4(0.f, 0.f, 0.f, 0.f);

    for (int cb = bbeg; cb < bend; cb += ACHUNK) {
        int cnt = min(ACHUNK, bend - cb);
        __syncthreads();
        for (int i = t; i < cnt; i += 256) {
            int g = cb + i;
            unsigned pk = g_edgep[g];
            sp[i] = pk;
            int src = (int)(pk & 0xFFFFu);
            int typ = (int)(pk >> 16);
            int nd = (g >= r1) + (g >= r2) + (g >= r3) + (g >= r4)
                   + (g >= r5) + (g >= r6) + (g >= r7);
            float4 s4 = *(const float4*)(g_ssrc + src * HH);
            float4 d4 = ssd[nd];
            float4 rr = sser[typ];
            float a0 = s4.x + d4.x + rr.x;
            float a1 = s4.y + d4.y + rr.y;
            float a2 = s4.z + d4.z + rr.z;
            float a3 = s4.w + d4.w + rr.w;
            a0 = (a0 > 0.f) ? a0 : 0.2f * a0;
            a1 = (a1 > 0.f) ? a1 : 0.2f * a1;
            a2 = (a2 > 0.f) ? a2 : 0.2f * a2;
            a3 = (a3 > 0.f) ? a3 : 0.2f * a3;
            sw4[i] = make_float4(__expf(a0), __expf(a1), __expf(a2), __expf(a3));
        }
        __syncthreads();
        int s = max(beg, cb);
        int e = min(end, cb + cnt);
        int j = s;
        for (; j + 1 < e; j += 2) {
            int li0 = j - cb, li1 = li0 + 1;
            unsigned p0 = sp[li0], p1 = sp[li1];
            uint2 rv0 = __ldg((const uint2*)(g_hh + (p0 & 0xFFFFu) * HC) + lane);
            uint2 rv1 = __ldg((const uint2*)(g_hh + (p1 & 0xFFFFu) * HC) + lane);
            float w0 = swf[li0 * 4 + hd];
            float w1 = swf[li1 * 4 + hd];
            float2 f00 = __half22float2(*(const __half2*)&rv0.x);
            float2 f01 = __half22float2(*(const __half2*)&rv0.y);
            float2 f10 = __half22float2(*(const __half2*)&rv1.x);
            float2 f11 = __half22float2(*(const __half2*)&rv1.y);
            ds0 += w0;
            ac0.x += w0 * f00.x; ac0.y += w0 * f00.y;
            ac0.z += w0 * f01.x; ac0.w += w0 * f01.y;
            ds1 += w1;
            ac1.x += w1 * f10.x; ac1.y += w1 * f10.y;
            ac1.z += w1 * f11.x; ac1.w += w1 * f11.y;
        }
        if (j < e) {
            int li = j - cb;
            unsigned p = sp[li];
            uint2 rv = __ldg((const uint2*)(g_hh + (p & 0xFFFFu) * HC) + lane);
            float w = swf[li * 4 + hd];
            float2 f0 = __half22float2(*(const __half2*)&rv.x);
            float2 f1 = __half22float2(*(const __half2*)&rv.y);
            ds0 += w;
            ac0.x += w * f0.x; ac0.y += w * f0.y;
            ac0.z += w * f1.x; ac0.w += w * f1.y;
        }
    }
    float inv = 1.f / (ds0 + ds1 + 1e-16f);
    float4 b4 = ((const float4*)bias)[lane];
    float4 xp = ((const float4*)xprev)[n * 32 + lane];
    float4 o = make_float4((ac0.x + ac1.x) * inv + b4.x + xp.x,
                           (ac0.y + ac1.y) * inv + b4.y + xp.y,
                           (ac0.z + ac1.z) * inv + b4.z + xp.z,
                           (ac0.w + ac1.w) * inv + b4.w + xp.w);
    o.x = fmaxf(o.x, 0.f); o.y = fmaxf(o.y, 0.f);
    o.z = fmaxf(o.z, 0.f); o.w = fmaxf(o.w, 0.f);
    ((float4*)xout)[n * 32 + lane] = o;
}

// ---------- wmma shared layouts (padded, conflict-free) ----------
#define LDA 72
#define LDB 136
#define LDC 132
union GemmSmem {
    struct { __half a[128 * LDA]; __half b[64 * LDB]; } in;
    float c[64 * LDC];
};

__device__ __forceinline__ void load_A_chunk(GemmSmem& sm, const float* __restrict__ A,
                                             int row0, int kc, int M, int t) {
    int r = t >> 1;
    int c0 = (t & 1) * 32;
    int gr = row0 + r;
    const float4* src = (const float4*)(A + gr * HC + kc + c0);
#pragma unroll
    for (int i = 0; i < 8; i++) {
        float4 v = (gr < M) ? src[i] : make_float4(0, 0, 0, 0);
        *(__half2*)&sm.in.a[r * LDA + c0 + i * 4]     = __floats2half2_rn(v.x, v.y);
        *(__half2*)&sm.in.a[r * LDA + c0 + i * 4 + 2] = __floats2half2_rn(v.z, v.w);
    }
}

// ---------- wmma GEMM + fused epilogue: h(fp16), s_src, s_dst ----------
__global__ void __launch_bounds__(256) k_gemm(const float* __restrict__ A,
                                              const float* __restrict__ B,
                                              const float* __restrict__ attS,
                                              const float* __restrict__ attD,
                                              int M) {
    __shared__ GemmSmem sm;
    __shared__ float sa[HC], sd[HC];
    int t = threadIdx.x;
    int w = t >> 5;
    int row0 = blockIdx.x * 128;
    if (t < HC) { sa[t] = attS[t]; sd[t] = attD[t]; }

    wmma::fragment<wmma::accumulator, 16, 16, 16, float> acc[8];
#pragma unroll
    for (int n = 0; n < 8; n++) wmma::fill_fragment(acc[n], 0.f);

    for (int kc = 0; kc < 128; kc += 64) {
        __syncthreads();
        load_A_chunk(sm, A, row0, kc, M, t);
        {
            int k = t >> 2;
            int c0 = (t & 3) * 32;
            const float4* src = (const float4*)(B + (kc + k) * HC + c0);
#pragma unroll
            for (int i = 0; i < 8; i++) {
                float4 v = src[i];
                *(__half2*)&sm.in.b[k * LDB + c0 + i * 4]     = __floats2half2_rn(v.x, v.y);
                *(__half2*)&sm.in.b[k * LDB + c0 + i * 4 + 2] = __floats2half2_rn(v.z, v.w);
            }
        }
        __syncthreads();
#pragma unroll
        for (int k4 = 0; k4 < 4; k4++) {
            wmma::fragment<wmma::matrix_a, 16, 16, 16, __half, wmma::row_major> af;
            wmma::load_matrix_sync(af, &sm.in.a[(w * 16) * LDA + k4 * 16], LDA);
#pragma unroll
            for (int n = 0; n < 8; n++) {
                wmma::fragment<wmma::matrix_b, 16, 16, 16, __half, wmma::row_major> bf;
                wmma::load_matrix_sync(bf, &sm.in.b[(k4 * 16) * LDB + n * 16], LDB);
                wmma::mma_sync(acc[n], af, bf, acc[n]);
            }
        }
    }
#pragma unroll
    for (int ph = 0; ph < 2; ph++) {
        __syncthreads();
        if ((w >> 2) == ph) {
            int wr = w & 3;
#pragma unroll
            for (int n = 0; n < 8; n++)
                wmma::store_matrix_sync(&sm.c[(wr * 16) * LDC + n * 16], acc[n], LDC,
                                        wmma::mem_row_major);
        }
        __syncthreads();
        int rl = t >> 2, hq = t & 3;
        int gr = row0 + ph * 64 + rl;
        if (gr < M) {
            float ps = 0.f, pd = 0.f;
            uint4 u[4];
#pragma unroll
            for (int q = 0; q < 4; q++) {
                float f[8];
#pragma unroll
                for (int j = 0; j < 8; j++) {
                    f[j] = sm.c[rl * LDC + hq * 32 + q * 8 + j];
                    ps += f[j] * sa[hq * 32 + q * 8 + j];
                    pd += f[j] * sd[hq * 32 + q * 8 + j];
                }
                __half2 h0 = __floats2half2_rn(f[0], f[1]);
                __half2 h1 = __floats2half2_rn(f[2], f[3]);
                __half2 h2 = __floats2half2_rn(f[4], f[5]);
                __half2 h3 = __floats2half2_rn(f[6], f[7]);
                u[q] = make_uint4(*(unsigned*)&h0, *(unsigned*)&h1,
                                  *(unsigned*)&h2, *(unsigned*)&h3);
            }
            uint4* dst = (uint4*)(g_hh + gr * HC + hq * 32);
            dst[0] = u[0]; dst[1] = u[1]; dst[2] = u[2]; dst[3] = u[3];
            g_ssrc[gr * HH + hq] = ps;
            g_sdst[gr * HH + hq] = pd;
        }
    }
}

// ---------- wmma fused MLP head ----------
__global__ void __launch_bounds__(256) k_mlp(const float* __restrict__ A,
                                             const float* __restrict__ W1,
                                             const float* __restrict__ b1,
                                             const float* __restrict__ W2,
                                             const float* __restrict__ b2,
                                             float* __restrict__ out, int M) {
    __shared__ GemmSmem sm;
    __shared__ float sw2[HC], sb1[HC];
    int t = threadIdx.x;
    int w = t >> 5;
    int row0 = blockIdx.x * 128;
    if (t < HC) {
        sw2[t] = (t < HID) ? W2[t] : 0.f;
        sb1[t] = (t < HID) ? b1[t] : 0.f;
    }
    wmma::fragment<wmma::accumulator, 16, 16, 16, float> acc[8];
#pragma unroll
    for (int n = 0; n < 8; n++) wmma::fill_fragment(acc[n], 0.f);

    for (int kc = 0; kc < 128; kc += 64) {
        __syncthreads();
        load_A_chunk(sm, A, row0, kc, M, t);
        {
            int k = t >> 2;
            int c0 = (t & 3) * 32;
#pragma unroll
            for (int i = 0; i < 32; i++) {
                int c = c0 + i;
                float v = (c < HID) ? W1[(kc + k) * HID + c] : 0.f;
                sm.in.b[k * LDB + c] = __float2half_rn(v);
            }
        }
        __syncthreads();
#pragma unroll
        for (int k4 = 0; k4 < 4; k4++) {
            wmma::fragment<wmma::matrix_a, 16, 16, 16, __half, wmma::row_major> af;
            wmma::load_matrix_sync(af, &sm.in.a[(w * 16) * LDA + k4 * 16], LDA);
#pragma unroll
            for (int n = 0; n < 8; n++) {
                wmma::fragment<wmma::matrix_b, 16, 16, 16, __half, wmma::row_major> bf;
                wmma::load_matrix_sync(bf, &sm.in.b[(k4 * 16) * LDB + n * 16], LDB);
                wmma::mma_sync(acc[n], af, bf, acc[n]);
            }
        }
    }
#pragma unroll
    for (int ph = 0; ph < 2; ph++) {
        __syncthreads();
        if ((w >> 2) == ph) {
            int wr = w & 3;
#pragma unroll
            for (int n = 0; n < 8; n++)
                wmma::store_matrix_sync(&sm.c[(wr * 16) * LDC + n * 16], acc[n], LDC,
                                        wmma::mem_row_major);
        }
        __syncthreads();
        int rl = t >> 2, hq = t & 3;
        int gr = row0 + ph * 64 + rl;
        float p = 0.f;
#pragma unroll
        for (int j = 0; j < 32; j++) {
            int c = hq * 32 + j;
            float v = fmaxf(sm.c[rl * LDC + c] + sb1[c], 0.f);
            p += v * sw2[c];
        }
        p += __shfl_xor_sync(0xffffffffu, p, 1);
        p += __shfl_xor_sync(0xffffffffu, p, 2);
        if ((t & 3) == 0 && gr < M)
            out[gr] = 1.f / (1.f + __expf(-(p + b2[0])));
    }
}

// ---------- host ----------
extern "C" void kernel_launch(void* const* d_in, const int* in_sizes, int n_in,
                              void* d_out, int out_size) {
    const float* x     = (const float*)d_in[0];
    const int*   ei    = (const int*)d_in[1];
    const int*   et    = (const int*)d_in[2];
    const float* eemb  = (const float*)d_in[3];
    const float* W0    = (const float*)d_in[4];
    const float* W1    = (const float*)d_in[5];
    const float* W2    = (const float*)d_in[6];
    const float* attS  = (const float*)d_in[7];
    const float* attD  = (const float*)d_in[8];
    const float* attE  = (const float*)d_in[9];
    const float* Wedge = (const float*)d_in[10];
    const float* bias  = (const float*)d_in[11];
    const float* mW1   = (const float*)d_in[12];
    const float* mb1   = (const float*)d_in[13];
    const float* mW2   = (const float*)d_in[14];
    const float* mb2   = (const float*)d_in[15];
    float* out = (float*)d_out;

    float *pxA, *pxB;
    cudaGetSymbolAddress((void**)&pxA, g_xA);
    cudaGetSymbolAddress((void**)&pxB, g_xB);

    // graph build; g_counts/g_hist arrive zeroed (re-zeroed by k_agg0 each call)
    k_histcount<<<(EE + 255) / 256, 256>>>(ei, et);
    k_scanpre<<<1, 1024>>>(W0, Wedge, attE, eemb, attS, attD);
    k_scatter<<<(EP + 255) / 256, 256>>>(ei, et);

    int gAgg = (NN + 7) / 8;
    int gGm  = (NN + 127) / 128;

    // layer 0: fully rank-1 aggregation (scores computed inline)
    k_agg0<<<gAgg, 256>>>(x, bias + 0 * HC, pxA);

    // layer 1
    k_gemm<<<gGm, 256>>>(pxA, W1, attS + 1 * HC, attD + 1 * HC, NN);
    k_agg<<<gAgg, 256>>>(bias + 1 * HC, pxA, pxB, 1);

    // layer 2
    k_gemm<<<gGm, 256>>>(pxB, W2, attS + 2 * HC, attD + 2 * HC, NN);
    k_agg<<<gAgg, 256>>>(bias + 2 * HC, pxB, pxA, 2);

    // fused MLP head
    k_mlp<<<gGm, 256>>>(pxA, mW1, mb1, mW2, mb2, out, NN);
}

// round 17
// speedup vs baseline: 1.0291x; 1.0291x over previous
#include <cuda_runtime.h>
#include <cuda_fp16.h>
#include <mma.h>
using namespace nvcuda;

#define NN 50000
#define EE 800000
#define EP (EE + NN)
#define HH 4
#define CC 32
#define HC 128
#define EDIM 8
#define NRELS 16
#define NLAYERS 3
#define HID 100

typedef unsigned long long ull;

static_assert(NN % 8 == 0, "agg blocks must be full");

// ---------- scratch (device globals; g_counts/g_hist zeroed steady-state) ----------
__device__ __half g_hh[NN * HC];
__device__ float g_xA[NN * HC];
__device__ float g_xB[NN * HC];
__device__ float g_ssrc[NN * HH];
__device__ float g_sdst[NN * HH];
__device__ int   g_rowstart[NN + 1];
__device__ int   g_counts[NN];
__device__ int   g_cursor[NN];
__device__ unsigned g_edgep[EP];        // src | (type<<16), sorted by dst
__device__ int   g_edst[EP];            // dst per CSR slot
__device__ float g_serel[NLAYERS * (NRELS + 1) * HH];
__device__ float g_w0sum[HC];
__device__ float g_k0[8];
__device__ int   g_hist[NRELS];

// ---------- build: counts + type histogram (counts arrive zeroed) ----------
__global__ void k_histcount(const int* __restrict__ ei, const int* __restrict__ et) {
    __shared__ int sh[NRELS];
    if (threadIdx.x < NRELS) sh[threadIdx.x] = 0;
    __syncthreads();
    int i = blockIdx.x * blockDim.x + threadIdx.x;
    if (i < EE) {
        atomicAdd(&g_counts[ei[EE + i]], 1);
        atomicAdd(&sh[et[i]], 1);
    }
    __syncthreads();
    if (threadIdx.x < NRELS) atomicAdd(&g_hist[threadIdx.x], sh[threadIdx.x]);
}

// ---------- fused: exclusive scan (+1 self-loop) THEN tiny precompute ----------
__global__ void k_scanpre(const float* __restrict__ W0, const float* __restrict__ Wedge,
                          const float* __restrict__ attE, const float* __restrict__ eemb,
                          const float* __restrict__ attS, const float* __restrict__ attD) {
    __shared__ int ss[1024];
    __shared__ float su[NLAYERS * HH * EDIM];
    __shared__ float sea[EDIM];
    __shared__ float sw0[HC];
    const int CH = (NN + 1023) / 1024;
    int t = threadIdx.x;
    int w = t >> 5, lane = t & 31;

    // ---- scan phase ----
    int beg = t * CH;
    int end = min(beg + CH, NN);
    int s = 0;
    for (int i = beg; i < end; i++) s += g_counts[i] + 1;
    ss[t] = s;
    __syncthreads();
    for (int off = 1; off < 1024; off <<= 1) {
        int v = 0;
        if (t >= off) v = ss[t - off];
        __syncthreads();
        ss[t] += v;
        __syncthreads();
    }
    int run = (t == 0) ? 0 : ss[t - 1];
    for (int i = beg; i < end; i++) {
        g_rowstart[i] = run;
        g_cursor[i]   = run;
        run += g_counts[i] + 1;
    }
    if (t == 0) g_rowstart[NN] = EP;

    // ---- pre phase ----
    if (t < HC) {
        float v = 0.f;
        for (int c = 0; c < CC; c++) v += W0[c * HC + t];
        g_w0sum[t] = v;
        sw0[t] = v;
    }
    for (int e = w; e < NLAYERS * HH * EDIM; e += 32) {
        int l = e >> 5;
        int rem = e & 31;
        int h = rem >> 3;
        int d = rem & 7;
        float v = Wedge[(l * EDIM + d) * HC + h * CC + lane] * attE[l * HC + h * CC + lane];
#pragma unroll
        for (int off = 16; off; off >>= 1) v += __shfl_xor_sync(0xffffffffu, v, off);
        if (lane == 0) su[e] = v;
    }
    if (t < EDIM) {
        float f = 0.f;
        for (int rr = 0; rr < NRELS; rr++)
            f += (float)g_hist[rr] * eemb[rr * EDIM + t];
        sea[t] = f / (float)EE;
    }
    __syncthreads();
    if (t < NLAYERS * (NRELS + 1) * HH) {
        int l = t / ((NRELS + 1) * HH);
        int rem = t % ((NRELS + 1) * HH);
        int r = rem / HH;
        int h = rem % HH;
        float v = 0.f;
#pragma unroll
        for (int d = 0; d < EDIM; d++) {
            float ea = (r < NRELS) ? eemb[r * EDIM + d] : sea[d];
            v += ea * su[l * 32 + h * EDIM + d];
        }
        g_serel[t] = v;
    }
    if (t < 8) {
        int h = t & 3;
        const float* av = (t < 4) ? attS : attD;
        float v = 0.f;
        for (int c = 0; c < CC; c++) v += sw0[h * CC + c] * av[h * CC + c];
        g_k0[t] = v;
    }
}

// ---------- scatter edges into dst-CSR ----------
__global__ void k_scatter(const int* __restrict__ ei, const int* __restrict__ et) {
    int i = blockIdx.x * blockDim.x + threadIdx.x;
    if (i < EE) {
        int d = ei[EE + i];
        int p = atomicAdd(&g_cursor[d], 1);
        g_edgep[p] = (unsigned)ei[i] | ((unsigned)et[i] << 16);
        g_edst[p] = d;
    } else if (i < EP) {
        int n = i - EE;
        int p = atomicAdd(&g_cursor[n], 1);
        g_edgep[p] = (unsigned)n | ((unsigned)NRELS << 16);
        g_edst[p] = n;
    }
}

// ---------- layer-0 aggregation: rank-1; edges split across the 8 lanes of
// each head group, butterfly merge. Re-zeroes g_counts / g_hist. ----------
__global__ void __launch_bounds__(256) k_agg0(const float* __restrict__ x,
                                              const float* __restrict__ bias,
                                              float* __restrict__ xout) {
    __shared__ float sser[(NRELS + 1) * HH];
    int t = threadIdx.x;
    if (t < (NRELS + 1) * HH) sser[t] = g_serel[t];
    if (blockIdx.x == 0 && t < NRELS) g_hist[t] = 0;
    __syncthreads();
    int warp = t >> 5, lane = t & 31;
    int n = blockIdx.x * 8 + warp;
    if (n >= NN) return;
    if (lane == 0) g_counts[n] = 0;
    int hd = lane >> 3;
    int sub = lane & 7;
    float4 w4 = ((const float4*)g_w0sum)[lane];
    float k0s = g_k0[hd];
    int beg = g_rowstart[n], end = g_rowstart[n + 1];
    float sdv = x[n] * g_k0[4 + hd];
    float ds = 0.f, sx = 0.f;

    for (int e = beg + sub; e < end; e += 8) {
        unsigned p = g_edgep[e];
        float xs = x[p & 0xFFFFu];
        float a = xs * k0s + sdv + sser[(p >> 16) * HH + hd];
        a = (a > 0.f) ? a : 0.2f * a;
        float w = __expf(a);
        ds += w;
        sx += w * xs;
    }
#pragma unroll
    for (int off = 1; off < 8; off <<= 1) {
        ds += __shfl_xor_sync(0xffffffffu, ds, off);
        sx += __shfl_xor_sync(0xffffffffu, sx, off);
    }
    float s = sx / (ds + 1e-16f);
    float4 b4 = ((const float4*)bias)[lane];
    float4 o = make_float4(fmaxf(s * w4.x + b4.x, 0.f), fmaxf(s * w4.y + b4.y, 0.f),
                           fmaxf(s * w4.z + b4.z, 0.f), fmaxf(s * w4.w + b4.w, 0.f));
    ((float4*)xout)[n * 32 + lane] = o;
}

// ---------- layers 1,2 aggregation: fused in-block edge scoring + gather,
// 4-deep gather unroll ----------
#define ACHUNK 512
__global__ void __launch_bounds__(256) k_agg(const float* __restrict__ bias,
                                             const float* __restrict__ xprev,
                                             float* __restrict__ xout, int layer) {
    __shared__ unsigned sp[ACHUNK];
    __shared__ float4 sw4[ACHUNK];
    __shared__ float4 sser[NRELS + 1];
    int t = threadIdx.x;
    if (t < NRELS + 1)
        sser[t] = *(const float4*)&g_serel[layer * (NRELS + 1) * HH + t * HH];
    int warp = t >> 5, lane = t & 31;
    int b0 = blockIdx.x * 8;
    int n = b0 + warp;
    int hd = lane >> 3;
    int beg = g_rowstart[n], end = g_rowstart[n + 1];
    int bbeg = g_rowstart[b0];
    int bend = g_rowstart[b0 + 8];
    const float* swf = (const float*)sw4;
    float ds0 = 0.f, ds1 = 0.f;
    float4 ac0 = make_float4(0.f, 0.f, 0.f, 0.f);
    float4 ac1 = make_float4(0.f, 0.f, 0.f, 0.f);

    for (int cb = bbeg; cb < bend; cb += ACHUNK) {
        int cnt = min(ACHUNK, bend - cb);
        __syncthreads();
        for (int i = t; i < cnt; i += 256) {
            unsigned pk = g_edgep[cb + i];
            sp[i] = pk;
            int src = (int)(pk & 0xFFFFu);
            int typ = (int)(pk >> 16);
            int dst = g_edst[cb + i];
            float4 s4 = *(const float4*)(g_ssrc + src * HH);
            float4 d4 = *(const float4*)(g_sdst + dst * HH);
            float4 r4 = sser[typ];
            float a0 = s4.x + d4.x + r4.x;
            float a1 = s4.y + d4.y + r4.y;
            float a2 = s4.z + d4.z + r4.z;
            float a3 = s4.w + d4.w + r4.w;
            a0 = (a0 > 0.f) ? a0 : 0.2f * a0;
            a1 = (a1 > 0.f) ? a1 : 0.2f * a1;
            a2 = (a2 > 0.f) ? a2 : 0.2f * a2;
            a3 = (a3 > 0.f) ? a3 : 0.2f * a3;
            sw4[i] = make_float4(__expf(a0), __expf(a1), __expf(a2), __expf(a3));
        }
        __syncthreads();
        int s = max(beg, cb);
        int e = min(end, cb + cnt);
        int j = s;
        // 4-deep unroll: 4 independent row gathers in flight per lane
        for (; j + 3 < e; j += 4) {
            int li0 = j - cb;
            unsigned p0 = sp[li0], p1 = sp[li0 + 1], p2 = sp[li0 + 2], p3 = sp[li0 + 3];
            uint2 rv0 = __ldg((const uint2*)(g_hh + (p0 & 0xFFFFu) * HC) + lane);
            uint2 rv1 = __ldg((const uint2*)(g_hh + (p1 & 0xFFFFu) * HC) + lane);
            uint2 rv2 = __ldg((const uint2*)(g_hh + (p2 & 0xFFFFu) * HC) + lane);
            uint2 rv3 = __ldg((const uint2*)(g_hh + (p3 & 0xFFFFu) * HC) + lane);
            float w0 = swf[li0 * 4 + hd];
            float w1 = swf[(li0 + 1) * 4 + hd];
            float w2 = swf[(li0 + 2) * 4 + hd];
            float w3 = swf[(li0 + 3) * 4 + hd];
            float2 f00 = __half22float2(*(const __half2*)&rv0.x);
            float2 f01 = __half22float2(*(const __half2*)&rv0.y);
            float2 f10 = __half22float2(*(const __half2*)&rv1.x);
            float2 f11 = __half22float2(*(const __half2*)&rv1.y);
            float2 f20 = __half22float2(*(const __half2*)&rv2.x);
            float2 f21 = __half22float2(*(const __half2*)&rv2.y);
            float2 f30 = __half22float2(*(const __half2*)&rv3.x);
            float2 f31 = __half22float2(*(const __half2*)&rv3.y);
            ds0 += w0;
            ac0.x += w0 * f00.x; ac0.y += w0 * f00.y;
            ac0.z += w0 * f01.x; ac0.w += w0 * f01.y;
            ds1 += w1;
            ac1.x += w1 * f10.x; ac1.y += w1 * f10.y;
            ac1.z += w1 * f11.x; ac1.w += w1 * f11.y;
            ds0 += w2;
            ac0.x += w2 * f20.x; ac0.y += w2 * f20.y;
            ac0.z += w2 * f21.x; ac0.w += w2 * f21.y;
            ds1 += w3;
            ac1.x += w3 * f30.x; ac1.y += w3 * f30.y;
            ac1.z += w3 * f31.x; ac1.w += w3 * f31.y;
        }
        for (; j < e; j++) {
            int li = j - cb;
            unsigned p = sp[li];
            uint2 rv = __ldg((const uint2*)(g_hh + (p & 0xFFFFu) * HC) + lane);
            float w = swf[li * 4 + hd];
            float2 f0 = __half22float2(*(const __half2*)&rv.x);
            float2 f1 = __half22float2(*(const __half2*)&rv.y);
            ds0 += w;
            ac0.x += w * f0.x; ac0.y += w * f0.y;
            ac0.z += w * f1.x; ac0.w += w * f1.y;
        }
    }
    float inv = 1.f / (ds0 + ds1 + 1e-16f);
    float4 b4 = ((const float4*)bias)[lane];
    float4 xp = ((const float4*)xprev)[n * 32 + lane];
    float4 o = make_float4((ac0.x + ac1.x) * inv + b4.x + xp.x,
                           (ac0.y + ac1.y) * inv + b4.y + xp.y,
                           (ac0.z + ac1.z) * inv + b4.z + xp.z,
                           (ac0.w + ac1.w) * inv + b4.w + xp.w);
    o.x = fmaxf(o.x, 0.f); o.y = fmaxf(o.y, 0.f);
    o.z = fmaxf(o.z, 0.f); o.w = fmaxf(o.w, 0.f);
    ((float4*)xout)[n * 32 + lane] = o;
}

// ---------- wmma shared layouts (padded, conflict-free) ----------
#define LDA 72
#define LDB 136
#define LDC 132
union GemmSmem {
    struct { __half a[128 * LDA]; __half b[64 * LDB]; } in;
    float c[64 * LDC];
};

__device__ __forceinline__ void load_A_chunk(GemmSmem& sm, const float* __restrict__ A,
                                             int row0, int kc, int M, int t) {
    int r = t >> 1;
    int c0 = (t & 1) * 32;
    int gr = row0 + r;
    const float4* src = (const float4*)(A + gr * HC + kc + c0);
#pragma unroll
    for (int i = 0; i < 8; i++) {
        float4 v = (gr < M) ? src[i] : make_float4(0, 0, 0, 0);
        *(__half2*)&sm.in.a[r * LDA + c0 + i * 4]     = __floats2half2_rn(v.x, v.y);
        *(__half2*)&sm.in.a[r * LDA + c0 + i * 4 + 2] = __floats2half2_rn(v.z, v.w);
    }
}

// ---------- wmma GEMM + fused epilogue: h(fp16), s_src, s_dst ----------
__global__ void __launch_bounds__(256) k_gemm(const float* __restrict__ A,
                                              const float* __restrict__ B,
                                              const float* __restrict__ attS,
                                              const float* __restrict__ attD,
                                              int M) {
    __shared__ GemmSmem sm;
    __shared__ float sa[HC], sd[HC];
    int t = threadIdx.x;
    int w = t >> 5;
    int row0 = blockIdx.x * 128;
    if (t < HC) { sa[t] = attS[t]; sd[t] = attD[t]; }

    wmma::fragment<wmma::accumulator, 16, 16, 16, float> acc[8];
#pragma unroll
    for (int n = 0; n < 8; n++) wmma::fill_fragment(acc[n], 0.f);

    for (int kc = 0; kc < 128; kc += 64) {
        __syncthreads();
        load_A_chunk(sm, A, row0, kc, M, t);
        {
            int k = t >> 2;
            int c0 = (t & 3) * 32;
            const float4* src = (const float4*)(B + (kc + k) * HC + c0);
#pragma unroll
            for (int i = 0; i < 8; i++) {
                float4 v = src[i];
                *(__half2*)&sm.in.b[k * LDB + c0 + i * 4]     = __floats2half2_rn(v.x, v.y);
                *(__half2*)&sm.in.b[k * LDB + c0 + i * 4 + 2] = __floats2half2_rn(v.z, v.w);
            }
        }
        __syncthreads();
#pragma unroll
        for (int k4 = 0; k4 < 4; k4++) {
            wmma::fragment<wmma::matrix_a, 16, 16, 16, __half, wmma::row_major> af;
            wmma::load_matrix_sync(af, &sm.in.a[(w * 16) * LDA + k4 * 16], LDA);
#pragma unroll
            for (int n = 0; n < 8; n++) {
                wmma::fragment<wmma::matrix_b, 16, 16, 16, __half, wmma::row_major> bf;
                wmma::load_matrix_sync(bf, &sm.in.b[(k4 * 16) * LDB + n * 16], LDB);
                wmma::mma_sync(acc[n], af, bf, acc[n]);
            }
        }
    }
#pragma unroll
    for (int ph = 0; ph < 2; ph++) {
        __syncthreads();
        if ((w >> 2) == ph) {
            int wr = w & 3;
#pragma unroll
            for (int n = 0; n < 8; n++)
                wmma::store_matrix_sync(&sm.c[(wr * 16) * LDC + n * 16], acc[n], LDC,
                                        wmma::mem_row_major);
        }
        __syncthreads();
        int rl = t >> 2, hq = t & 3;
        int gr = row0 + ph * 64 + rl;
        if (gr < M) {
            float ps = 0.f, pd = 0.f;
            uint4 u[4];
#pragma unroll
            for (int q = 0; q < 4; q++) {
                float f[8];
#pragma unroll
                for (int j = 0; j < 8; j++) {
                    f[j] = sm.c[rl * LDC + hq * 32 + q * 8 + j];
                    ps += f[j] * sa[hq * 32 + q * 8 + j];
                    pd += f[j] * sd[hq * 32 + q * 8 + j];
                }
                __half2 h0 = __floats2half2_rn(f[0], f[1]);
                __half2 h1 = __floats2half2_rn(f[2], f[3]);
                __half2 h2 = __floats2half2_rn(f[4], f[5]);
                __half2 h3 = __floats2half2_rn(f[6], f[7]);
                u[q] = make_uint4(*(unsigned*)&h0, *(unsigned*)&h1,
                                  *(unsigned*)&h2, *(unsigned*)&h3);
            }
            uint4* dst = (uint4*)(g_hh + gr * HC + hq * 32);
            dst[0] = u[0]; dst[1] = u[1]; dst[2] = u[2]; dst[3] = u[3];
            g_ssrc[gr * HH + hq] = ps;
            g_sdst[gr * HH + hq] = pd;
        }
    }
}

// ---------- wmma fused MLP head ----------
__global__ void __launch_bounds__(256) k_mlp(const float* __restrict__ A,
                                             const float* __restrict__ W1,
                                             const float* __restrict__ b1,
                                             const float* __restrict__ W2,
                                             const float* __restrict__ b2,
                                             float* __restrict__ out, int M) {
    __shared__ GemmSmem sm;
    __shared__ float sw2[HC], sb1[HC];
    int t = threadIdx.x;
    int w = t >> 5;
    int row0 = blockIdx.x * 128;
    if (t < HC) {
        sw2[t] = (t < HID) ? W2[t] : 0.f;
        sb1[t] = (t < HID) ? b1[t] : 0.f;
    }
    wmma::fragment<wmma::accumulator, 16, 16, 16, float> acc[8];
#pragma unroll
    for (int n = 0; n < 8; n++) wmma::fill_fragment(acc[n], 0.f);

    for (int kc = 0; kc < 128; kc += 64) {
        __syncthreads();
        load_A_chunk(sm, A, row0, kc, M, t);
        {
            int k = t >> 2;
            int c0 = (t & 3) * 32;
#pragma unroll
            for (int i = 0; i < 32; i++) {
                int c = c0 + i;
                float v = (c < HID) ? W1[(kc + k) * HID + c] : 0.f;
                sm.in.b[k * LDB + c] = __float2half_rn(v);
            }
        }
        __syncthreads();
#pragma unroll
        for (int k4 = 0; k4 < 4; k4++) {
            wmma::fragment<wmma::matrix_a, 16, 16, 16, __half, wmma::row_major> af;
            wmma::load_matrix_sync(af, &sm.in.a[(w * 16) * LDA + k4 * 16], LDA);
#pragma unroll
            for (int n = 0; n < 8; n++) {
                wmma::fragment<wmma::matrix_b, 16, 16, 16, __half, wmma::row_major> bf;
                wmma::load_matrix_sync(bf, &sm.in.b[(k4 * 16) * LDB + n * 16], LDB);
                wmma::mma_sync(acc[n], af, bf, acc[n]);
            }
        }
    }
#pragma unroll
    for (int ph = 0; ph < 2; ph++) {
        __syncthreads();
        if ((w >> 2) == ph) {
            int wr = w & 3;
#pragma unroll
            for (int n = 0; n < 8; n++)
                wmma::store_matrix_sync(&sm.c[(wr * 16) * LDC + n * 16], acc[n], LDC,
                                        wmma::mem_row_major);
        }
        __syncthreads();
        int rl = t >> 2, hq = t & 3;
        int gr = row0 + ph * 64 + rl;
        float p = 0.f;
#pragma unroll
        for (int j = 0; j < 32; j++) {
            int c = hq * 32 + j;
            float v = fmaxf(sm.c[rl * LDC + c] + sb1[c], 0.f);
            p += v * sw2[c];
        }
        p += __shfl_xor_sync(0xffffffffu, p, 1);
        p += __shfl_xor_sync(0xffffffffu, p, 2);
        if ((t & 3) == 0 && gr < M)
            out[gr] = 1.f / (1.f + __expf(-(p + b2[0])));
    }
}

// ---------- host ----------
extern "C" void kernel_launch(void* const* d_in, const int* in_sizes, int n_in,
                              void* d_out, int out_size) {
    const float* x     = (const float*)d_in[0];
    const int*   ei    = (const int*)d_in[1];
    const int*   et    = (const int*)d_in[2];
    const float* eemb  = (const float*)d_in[3];
    const float* W0    = (const float*)d_in[4];
    const float* W1    = (const float*)d_in[5];
    const float* W2    = (const float*)d_in[6];
    const float* attS  = (const float*)d_in[7];
    const float* attD  = (const float*)d_in[8];
    const float* attE  = (const float*)d_in[9];
    const float* Wedge = (const float*)d_in[10];
    const float* bias  = (const float*)d_in[11];
    const float* mW1   = (const float*)d_in[12];
    const float* mb1   = (const float*)d_in[13];
    const float* mW2   = (const float*)d_in[14];
    const float* mb2   = (const float*)d_in[15];
    float* out = (float*)d_out;

    float *pxA, *pxB;
    cudaGetSymbolAddress((void**)&pxA, g_xA);
    cudaGetSymbolAddress((void**)&pxB, g_xB);

    // graph build; g_counts/g_hist arrive zeroed (re-zeroed by k_agg0 each call)
    k_histcount<<<(EE + 255) / 256, 256>>>(ei, et);
    k_scanpre<<<1, 1024>>>(W0, Wedge, attE, eemb, attS, attD);
    k_scatter<<<(EP + 255) / 256, 256>>>(ei, et);

    int gAgg = (NN + 7) / 8;
    int gGm  = (NN + 127) / 128;

    // layer 0: fully rank-1 aggregation (scores computed inline)
    k_agg0<<<gAgg, 256>>>(x, bias + 0 * HC, pxA);

    // layer 1
    k_gemm<<<gGm, 256>>>(pxA, W1, attS + 1 * HC, attD + 1 * HC, NN);
    k_agg<<<gAgg, 256>>>(bias + 1 * HC, pxA, pxB, 1);

    // layer 2
    k_gemm<<<gGm, 256>>>(pxB, W2, attS + 2 * HC, attD + 2 * HC, NN);
    k_agg<<<gAgg, 256>>>(bias + 2 * HC, pxB, pxA, 2);

    // fused MLP head
    k_mlp<<<gGm, 256>>>(pxA, mW1, mb1, mW2, mb2, out, NN);
}